// round 1
// baseline (speedup 1.0000x reference)
#include <cuda_runtime.h>
#include <cstddef>

// ---------------- problem constants ----------------
#define B_   32
#define T_   128
#define P_   4
#define DIN_ 512
#define H_   512
#define C_   4096
#define G_   16384   // 4*C
#define NSPLIT 8

// ---------------- device scratch (zero-initialized at module load) ----------------
__device__ float g_pi[(size_t)B_ * T_ * G_];       // 268 MB: input projection [b*T+t][4C]
__device__ float g_mem[(size_t)T_ * B_ * C_];      // 67 MB:  mem buffer [t][b][c]
__device__ float g_st [(size_t)T_ * B_ * H_];      // 8.4 MB: state buffer [t][b][h]
__device__ float g_a  [B_ * C_];                   // o*tanh(mem) per step
__device__ float g_hpart[NSPLIT * B_ * H_];        // split-K partials for projection

// ---------------- f32x2 packed-math helpers (sm_103a) ----------------
__device__ __forceinline__ unsigned long long pack2(float a, float b) {
    unsigned long long d;
    unsigned x = __float_as_uint(a), y = __float_as_uint(b);
    asm("mov.b64 %0, {%1,%2};" : "=l"(d) : "r"(x), "r"(y));
    return d;
}
__device__ __forceinline__ void unpack2(unsigned long long s, float& a, float& b) {
    unsigned x, y;
    asm("mov.b64 {%0,%1}, %2;" : "=r"(x), "=r"(y) : "l"(s));
    a = __uint_as_float(x); b = __uint_as_float(y);
}
__device__ __forceinline__ unsigned long long fma2(unsigned long long a,
                                                   unsigned long long b,
                                                   unsigned long long c) {
    unsigned long long d;
    asm("fma.rn.f32x2 %0, %1, %2, %3;" : "=l"(d) : "l"(a), "l"(b), "l"(c));
    return d;
}

__device__ __forceinline__ float sigmoidf(float x) {
    return 1.0f / (1.0f + __expf(-x));
}

// =====================================================================
// Kernel 1: proj_in = x @ W_in^T     [4096 x 512] * [16384 x 512]^T
// 128x128 tile per block, 256 threads, 8x8 micro-tile, f32x2 FMAs.
// =====================================================================
__global__ void __launch_bounds__(256) proj_in_kernel(const float* __restrict__ x,
                                                      const float* __restrict__ W_in) {
    __shared__ __align__(16) float As[16][128];
    __shared__ __align__(16) float Bs[16][128];

    const int tid = threadIdx.x;
    const int m0 = blockIdx.y * 128;
    const int n0 = blockIdx.x * 128;
    const int tm = tid >> 4;     // 0..15
    const int tn = tid & 15;     // 0..15

    unsigned long long acc[8][4];
#pragma unroll
    for (int i = 0; i < 8; i++)
#pragma unroll
        for (int j = 0; j < 4; j++) acc[i][j] = 0ull;

    for (int kk = 0; kk < DIN_; kk += 16) {
#pragma unroll
        for (int r = 0; r < 2; r++) {
            int f   = tid + r * 256;         // 0..511 float4 slots
            int row = f >> 2;                // 0..127
            int kq  = f & 3;                 // 0..3
            float4 va = *(const float4*)&x[(size_t)(m0 + row) * DIN_ + kk + kq * 4];
            As[kq * 4 + 0][row] = va.x;
            As[kq * 4 + 1][row] = va.y;
            As[kq * 4 + 2][row] = va.z;
            As[kq * 4 + 3][row] = va.w;
            float4 vb = *(const float4*)&W_in[(size_t)(n0 + row) * DIN_ + kk + kq * 4];
            Bs[kq * 4 + 0][row] = vb.x;
            Bs[kq * 4 + 1][row] = vb.y;
            Bs[kq * 4 + 2][row] = vb.z;
            Bs[kq * 4 + 3][row] = vb.w;
        }
        __syncthreads();
#pragma unroll
        for (int k = 0; k < 16; k++) {
            float4 a0 = *(const float4*)&As[k][tm * 8];
            float4 a1 = *(const float4*)&As[k][tm * 8 + 4];
            ulonglong2 b0 = *(const ulonglong2*)&Bs[k][tn * 8];
            ulonglong2 b1 = *(const ulonglong2*)&Bs[k][tn * 8 + 4];
            float av[8] = {a0.x, a0.y, a0.z, a0.w, a1.x, a1.y, a1.z, a1.w};
#pragma unroll
            for (int i = 0; i < 8; i++) {
                unsigned long long pa = pack2(av[i], av[i]);
                acc[i][0] = fma2(pa, b0.x, acc[i][0]);
                acc[i][1] = fma2(pa, b0.y, acc[i][1]);
                acc[i][2] = fma2(pa, b1.x, acc[i][2]);
                acc[i][3] = fma2(pa, b1.y, acc[i][3]);
            }
        }
        __syncthreads();
    }

#pragma unroll
    for (int i = 0; i < 8; i++) {
        float o[8];
        unpack2(acc[i][0], o[0], o[1]);
        unpack2(acc[i][1], o[2], o[3]);
        unpack2(acc[i][2], o[4], o[5]);
        unpack2(acc[i][3], o[6], o[7]);
        size_t base = (size_t)(m0 + tm * 8 + i) * G_ + n0 + tn * 8;
        float4 w0 = make_float4(o[0], o[1], o[2], o[3]);
        float4 w1 = make_float4(o[4], o[5], o[6], o[7]);
        *(float4*)&g_pi[base]     = w0;
        *(float4*)&g_pi[base + 4] = w1;
    }
}

// =====================================================================
// Kernel 2 (per step t): fused pool(state) -> g-GEMM -> gates -> mem.
// grid = 128 blocks (c-tile of 32 columns, all 4 gates, all 32 batches).
// Each thread owns (1 column c) x (4 gates) x (4 batches).
// smem: pooled prev_st [512][pad36], W_state k-chunk [16][128], idx/w.
// =====================================================================
#define GATE_SMEM_FLOATS (512 * 36 + 16 * 128 + 128 + 128)

__global__ void gate_kernel(int t,
                            const int*   __restrict__ prev_idx,
                            const float* __restrict__ prev_w,
                            const float* __restrict__ W_state,
                            const float* __restrict__ b_state) {
    extern __shared__ __align__(16) float sm[];
    float* s_pst = sm;                       // [h][b] stride 36
    float* s_ws  = sm + 512 * 36;            // [k][j] stride 128, k-chunk of 16
    float* s_w   = s_ws + 16 * 128;          // [b*4+p]
    int*   s_idx = (int*)(s_w + 128);        // [b*4+p]

    const int tid = threadIdx.x;
    const int c0  = blockIdx.x * 32;
    const int cl  = tid & 31;    // column within tile
    const int bg  = tid >> 5;    // batch group (4 batches each)

    // ---- load predecessor indices/weights for this step ----
    if (tid < 128) {
        int b = tid >> 2, p = tid & 3;
        s_idx[tid] = prev_idx[(b * T_ + t) * P_ + p];
        s_w[tid]   = prev_w [(b * T_ + t) * P_ + p];
    }
    __syncthreads();

    // ---- pool prev_st into smem: s_pst[h*36 + b] ----
#pragma unroll 4
    for (int i = 0; i < 64; i++) {
        int e = i * 256 + tid;          // 0..16383
        int b = e >> 9;                 // 0..31
        int h = e & 511;
        float acc = 0.0f;
#pragma unroll
        for (int p = 0; p < P_; p++) {
            int ip = s_idx[b * 4 + p];
            acc += s_w[b * 4 + p] * g_st[((size_t)ip * B_ + b) * H_ + h];
        }
        s_pst[h * 36 + b] = acc;
    }
    __syncthreads();

    // ---- GEMM: g[j, b] = sum_h W_state[j,h] * pst[h,b],  j-tile = 4 gates x 32 c ----
    unsigned long long acc[4][2];
#pragma unroll
    for (int gidx = 0; gidx < 4; gidx++) { acc[gidx][0] = 0ull; acc[gidx][1] = 0ull; }

    for (int kk = 0; kk < H_; kk += 16) {
#pragma unroll
        for (int r = 0; r < 2; r++) {
            int f  = tid + r * 256;      // 0..511 float4 slots (128 rows x 4 f4/row)
            int jl = f >> 2;             // 0..127
            int kq = f & 3;
            int row = (jl >> 5) * C_ + c0 + (jl & 31);   // gate*C + c
            float4 v = *(const float4*)&W_state[(size_t)row * H_ + kk + kq * 4];
            s_ws[(kq * 4 + 0) * 128 + jl] = v.x;
            s_ws[(kq * 4 + 1) * 128 + jl] = v.y;
            s_ws[(kq * 4 + 2) * 128 + jl] = v.z;
            s_ws[(kq * 4 + 3) * 128 + jl] = v.w;
        }
        __syncthreads();
#pragma unroll
        for (int k = 0; k < 16; k++) {
            ulonglong2 pb = *(const ulonglong2*)&s_pst[(kk + k) * 36 + bg * 4];
            float w0 = s_ws[k * 128 +  0 + cl];
            float w1 = s_ws[k * 128 + 32 + cl];
            float w2 = s_ws[k * 128 + 64 + cl];
            float w3 = s_ws[k * 128 + 96 + cl];
            unsigned long long pw;
            pw = pack2(w0, w0); acc[0][0] = fma2(pw, pb.x, acc[0][0]); acc[0][1] = fma2(pw, pb.y, acc[0][1]);
            pw = pack2(w1, w1); acc[1][0] = fma2(pw, pb.x, acc[1][0]); acc[1][1] = fma2(pw, pb.y, acc[1][1]);
            pw = pack2(w2, w2); acc[2][0] = fma2(pw, pb.x, acc[2][0]); acc[2][1] = fma2(pw, pb.y, acc[2][1]);
            pw = pack2(w3, w3); acc[3][0] = fma2(pw, pb.x, acc[3][0]); acc[3][1] = fma2(pw, pb.y, acc[3][1]);
        }
        __syncthreads();
    }

    // ---- epilogue: gates, mem update, a = o*tanh(mem) ----
    float ga[4][4];
#pragma unroll
    for (int gidx = 0; gidx < 4; gidx++) {
        unpack2(acc[gidx][0], ga[gidx][0], ga[gidx][1]);
        unpack2(acc[gidx][1], ga[gidx][2], ga[gidx][3]);
    }
    const int c = c0 + cl;
#pragma unroll
    for (int bb = 0; bb < 4; bb++) {
        const int b = bg * 4 + bb;
        const size_t pibase = (size_t)(b * T_ + t) * G_;
        float gi = ga[0][bb] + g_pi[pibase + 0 * (size_t)C_ + c] + b_state[0 * C_ + c];
        float gf = ga[1][bb] + g_pi[pibase + 1 * (size_t)C_ + c] + b_state[1 * C_ + c];
        float gm = ga[2][bb] + g_pi[pibase + 2 * (size_t)C_ + c] + b_state[2 * C_ + c];
        float go = ga[3][bb] + g_pi[pibase + 3 * (size_t)C_ + c] + b_state[3 * C_ + c];

        float pmem = 0.0f;
#pragma unroll
        for (int p = 0; p < P_; p++) {
            int ip = s_idx[b * 4 + p];
            pmem += s_w[b * 4 + p] * g_mem[((size_t)ip * B_ + b) * C_ + c];
        }
        float ig = sigmoidf(gi);
        float fg = sigmoidf(gf);
        float mi = tanhf(gm);
        float og = sigmoidf(go);
        float mem = fminf(3.0f, fmaxf(-3.0f, ig * mi + fg * pmem));
        g_mem[((size_t)t * B_ + b) * C_ + c] = mem;
        g_a[b * C_ + c] = og * tanhf(mem);
    }
}

// =====================================================================
// Kernel 3 (per step): split-K projection partials.
// grid = (16 j-tiles of 32) x (8 K-chunks of 512). Deterministic (no atomics).
// =====================================================================
__global__ void __launch_bounds__(256) proj_part_kernel(const float* __restrict__ W_proj) {
    __shared__ __align__(16) float s_a [16 * 36];   // [k][b] pad 36
    __shared__ __align__(16) float s_wp[16 * 36];   // [k][j] pad 36

    const int tid = threadIdx.x;
    const int jl  = tid & 31;
    const int bg  = tid >> 5;
    const int j0    = blockIdx.x * 32;
    const int kbase = blockIdx.y * 512;

    unsigned long long acc0 = 0ull, acc1 = 0ull;

    for (int kk = 0; kk < 512; kk += 16) {
#pragma unroll
        for (int r = 0; r < 2; r++) {
            int e = tid + r * 256;     // 0..511
            int row = e >> 4;          // 0..31 (b or j)
            int k   = e & 15;
            s_a [k * 36 + row] = g_a[row * C_ + kbase + kk + k];
            s_wp[k * 36 + row] = W_proj[(size_t)(j0 + row) * C_ + kbase + kk + k];
        }
        __syncthreads();
#pragma unroll
        for (int k = 0; k < 16; k++) {
            float w = s_wp[k * 36 + jl];
            ulonglong2 pb = *(const ulonglong2*)&s_a[k * 36 + bg * 4];
            unsigned long long pw = pack2(w, w);
            acc0 = fma2(pw, pb.x, acc0);
            acc1 = fma2(pw, pb.y, acc1);
        }
        __syncthreads();
    }

    float h0, h1, h2, h3;
    unpack2(acc0, h0, h1);
    unpack2(acc1, h2, h3);
    const int b = bg * 4;
    const int ks = blockIdx.y;
    g_hpart[((ks * B_ + b + 0) * H_) + j0 + jl] = h0;
    g_hpart[((ks * B_ + b + 1) * H_) + j0 + jl] = h1;
    g_hpart[((ks * B_ + b + 2) * H_) + j0 + jl] = h2;
    g_hpart[((ks * B_ + b + 3) * H_) + j0 + jl] = h3;
}

// =====================================================================
// Kernel 4 (per step): reduce partials, clip, write st_buf[t] and out.
// =====================================================================
__global__ void finalize_kernel(int t, float* __restrict__ out) {
    int e = blockIdx.x * blockDim.x + threadIdx.x;   // 0..16383
    int b = e >> 9;
    int h = e & 511;
    float s = 0.0f;
#pragma unroll
    for (int ks = 0; ks < NSPLIT; ks++) s += g_hpart[(ks * B_ + b) * H_ + h];
    s = fminf(3.0f, fmaxf(-3.0f, s));
    g_st[((size_t)t * B_ + b) * H_ + h] = s;
    out[((size_t)b * T_ + t) * H_ + h]  = s;
}

// =====================================================================
// launch
// =====================================================================
extern "C" void kernel_launch(void* const* d_in, const int* in_sizes, int n_in,
                              void* d_out, int out_size) {
    const float* x        = (const float*)d_in[0];
    const int*   prev_idx = (const int*)  d_in[1];
    const float* prev_w   = (const float*)d_in[2];
    const float* W_in     = (const float*)d_in[3];
    const float* W_state  = (const float*)d_in[4];
    const float* b_state  = (const float*)d_in[5];
    const float* W_proj   = (const float*)d_in[6];
    float* out = (float*)d_out;

    (void)in_sizes; (void)n_in; (void)out_size;

    const int gate_smem = GATE_SMEM_FLOATS * (int)sizeof(float);
    cudaFuncSetAttribute(gate_kernel, cudaFuncAttributeMaxDynamicSharedMemorySize, gate_smem);

    // input projection (recurrence-free)
    proj_in_kernel<<<dim3(G_ / 128, (B_ * T_) / 128), 256>>>(x, W_in);

    // sequential lattice scan
    for (int t = 0; t < T_; t++) {
        gate_kernel<<<C_ / 32, 256, gate_smem>>>(t, prev_idx, prev_w, W_state, b_state);
        proj_part_kernel<<<dim3(H_ / 32, NSPLIT), 256>>>(W_proj);
        finalize_kernel<<<16, 1024>>>(t, out);
    }
}